// round 1
// baseline (speedup 1.0000x reference)
#include <cuda_runtime.h>
#include <math.h>

#define V 720
#define U 736
#define NXY 512
#define NTAPS 368           // odd taps: n = 1,3,...,735

static __constant__ double kPI = 3.14159265358979323846;

// geometry (double for table setup, float for hot loops)
#define DU_D   1.2858
#define DSO_D  595.0
#define DOD_D  490.6
#define DSD_D  (DSO_D + DOD_D)
#define SVOX_F 400.0f

// ---- device-global scratch (no allocations allowed) ----
__device__ float g_cb[V];
__device__ float g_sb[V];
__device__ float g_ho[NTAPS];     // -1/(pi*n*DU)^2 for odd n
__device__ float g_Q[V * U];      // filtered projections

// ---------------------------------------------------------------------------
// Kernel 0: per-view cos/sin table + ramp-filter odd-tap coefficients
// ---------------------------------------------------------------------------
__global__ void init_tables_kernel() {
    int i = blockIdx.x * blockDim.x + threadIdx.x;
    if (i < V) {
        // match reference: betas = float32(linspace(0, 2pi, V, endpoint=False))
        float bf = (float)(2.0 * kPI * (double)i / (double)V);
        g_cb[i] = (float)cos((double)bf);
        g_sb[i] = (float)sin((double)bf);
    }
    if (i < NTAPS) {
        double n = 2.0 * (double)i + 1.0;
        double d = kPI * n * DU_D;
        g_ho[i] = (float)(-1.0 / (d * d));
    }
}

// ---------------------------------------------------------------------------
// Kernel 1: cosine weighting + direct Ram-Lak convolution (odd taps only).
// One block per view. Shared: zero-padded weighted row + tap table.
// Q[u] = DU * ( h0*w[u] + sum_{odd n} (w[u-n]+w[u+n]) * (-1/(pi n DU)^2) )
// ---------------------------------------------------------------------------
#define WPAD (U + 2 * (U - 1))   // 2206

__global__ void filter_kernel(const float* __restrict__ sino) {
    __shared__ float wpad[WPAD];
    __shared__ float ho[NTAPS];

    const int v = blockIdx.x;
    const float* row = sino + v * U;

    for (int i = threadIdx.x; i < WPAD; i += blockDim.x) wpad[i] = 0.0f;
    for (int i = threadIdx.x; i < NTAPS; i += blockDim.x) ho[i] = g_ho[i];
    __syncthreads();

    const float dsd  = (float)DSD_D;
    const float dsd2 = (float)(DSD_D * DSD_D);
    const float du   = (float)DU_D;
    for (int u = threadIdx.x; u < U; u += blockDim.x) {
        float us = ((float)u - (float)(U - 1) * 0.5f) * du;
        wpad[(U - 1) + u] = row[u] * (dsd * rsqrtf(dsd2 + us * us));
    }
    __syncthreads();

    const float h0 = (float)(1.0 / (4.0 * DU_D * DU_D));
    for (int u = threadIdx.x; u < U; u += blockDim.x) {
        const float* wc = wpad + (U - 1) + u;
        float acc = h0 * wc[0];
        #pragma unroll 8
        for (int k = 0; k < NTAPS; k++) {
            int n = 2 * k + 1;
            acc += (wc[-n] + wc[n]) * ho[k];
        }
        g_Q[v * U + u] = acc * du;
    }
}

// ---------------------------------------------------------------------------
// Kernel 2: weighted fan-beam backprojection.
// threadIdx.x -> iy (contiguous output dim), loop over all 720 views.
// ---------------------------------------------------------------------------
__global__ void bp_kernel(float* __restrict__ out) {
    __shared__ float scb[V];
    __shared__ float ssb[V];

    const int tid = threadIdx.y * blockDim.x + threadIdx.x;
    const int nth = blockDim.x * blockDim.y;
    for (int i = tid; i < V; i += nth) { scb[i] = g_cb[i]; ssb[i] = g_sb[i]; }
    __syncthreads();

    const int iy = blockIdx.x * blockDim.x + threadIdx.x;
    const int ix = blockIdx.y * blockDim.y + threadIdx.y;

    const float dx = SVOX_F / (float)NXY;
    const float x = ((float)ix - (float)(NXY - 1) * 0.5f) * dx;
    const float y = ((float)iy - (float)(NXY - 1) * 0.5f) * dx;

    const float c0      = (float)(U - 1) * 0.5f;
    const float kDSD_DU = (float)(DSD_D / DU_D);
    const float dso     = (float)DSO_D;
    const float uMax    = (float)(U - 1);

    float acc = 0.0f;
    #pragma unroll 4
    for (int v = 0; v < V; v++) {
        float cb = scb[v], sb = ssb[v];
        float t = x * cb + y * sb;
        float s = -x * sb + y * cb;
        float D = dso - s;
        float r = __frcp_rn(D);              // D in [~312, ~878] — safe
        float idx = kDSD_DU * t * r + c0;
        float fi = floorf(idx);
        int i0 = (int)fi;
        i0 = max(0, min(U - 2, i0));
        float f = idx - (float)i0;
        const float* q = g_Q + v * U;
        float val = q[i0] * (1.0f - f) + q[i0 + 1] * f;
        float w = dso * r;
        bool ok = (idx >= 0.0f) && (idx <= uMax);
        acc += ok ? (w * w) * val : 0.0f;
    }

    const float scale = (float)(0.5 * (2.0 * 3.14159265358979323846 / (double)V));
    out[ix * NXY + iy] = acc * scale;
}

// ---------------------------------------------------------------------------
extern "C" void kernel_launch(void* const* d_in, const int* in_sizes, int n_in,
                              void* d_out, int out_size) {
    (void)in_sizes; (void)n_in; (void)out_size;
    const float* sino = (const float*)d_in[0];
    float* out = (float*)d_out;

    init_tables_kernel<<<3, 256>>>();
    filter_kernel<<<V, 256>>>(sino);
    dim3 bpBlock(32, 8);
    dim3 bpGrid(NXY / 32, NXY / 8);
    bp_kernel<<<bpGrid, bpBlock>>>(out);
}